// round 14
// baseline (speedup 1.0000x reference)
#include <cuda_runtime.h>
#include <cuda_fp16.h>
#include <cstdint>

// CFConv fused via mma.sync fp16 (m16n8k16, fp32 accum). Warp-autonomous
// 32-edge slices; hidden passed GEMM1 -> GEMM2 in registers; biases via mma
// C-operands; softplus constants folded into W1/b1 and W2. Epilogue routes
// the filter through a tiny fp16 smem transpose so the nw gather and the
// out scatter are fully coalesced per edge (1 line-pair per instruction,
// instead of 8 scattered lines).
// out[dst] += nw[src] * ( ssp(rbf @ W1 + b1) @ W2 + b2 )

static constexpr int TILE    = 256;
static constexpr int THREADS = 256;
static constexpr int STRIDE  = 72;    // fp32 row stride (conflict-free LDS.64)

// shared layout (floats)
static constexpr int SBUF_OFF = 0;                    // 256 x 72 fp32
static constexpr int W1F_OFF  = TILE * STRIDE;        // 18432: 512 uint4 fp16 frags
static constexpr int W2F_OFF  = W1F_OFF + 2048;       // 20480
static constexpr int B1_OFF   = W2F_OFF + 2048;       // 22528
static constexpr int B2_OFF   = B1_OFF + 64;          // 22592
static constexpr int SMEM_FLOATS = B2_OFF + 64;       // 22656
static constexpr int SMEM_BYTES  = SMEM_FLOATS * 4;   // 90624

static constexpr float K_IN  = 0.72134752f;   // 1/(2 ln 2)
static constexpr float K_OUT = 1.38629436f;   // 2 ln 2

__device__ __forceinline__ uint32_t h2(float lo, float hi) {
    uint32_t d;   // first PTX src -> upper half
    asm("cvt.rn.f16x2.f32 %0, %1, %2;" : "=r"(d) : "f"(hi), "f"(lo));
    return d;
}
__device__ __forceinline__ uint32_t h2f2(float2 p) { return h2(p.x, p.y); }

__device__ __forceinline__ void mma16(float c[4], const uint32_t a[4],
                                      uint32_t b0, uint32_t b1) {
    asm volatile(
        "mma.sync.aligned.m16n8k16.row.col.f32.f16.f16.f32 "
        "{%0,%1,%2,%3}, {%4,%5,%6,%7}, {%8,%9}, {%0,%1,%2,%3};"
        : "+f"(c[0]), "+f"(c[1]), "+f"(c[2]), "+f"(c[3])
        : "r"(a[0]), "r"(a[1]), "r"(a[2]), "r"(a[3]), "r"(b0), "r"(b1));
}

// first K-step: D = A*B + {cx,cy,cx,cy}  (bias injected via C operand)
__device__ __forceinline__ void mma16c(float d[4], const uint32_t a[4],
                                       uint32_t b0, uint32_t b1,
                                       float cx, float cy) {
    asm volatile(
        "mma.sync.aligned.m16n8k16.row.col.f32.f16.f16.f32 "
        "{%0,%1,%2,%3}, {%4,%5,%6,%7}, {%8,%9}, {%10,%11,%10,%11};"
        : "=f"(d[0]), "=f"(d[1]), "=f"(d[2]), "=f"(d[3])
        : "r"(a[0]), "r"(a[1]), "r"(a[2]), "r"(a[3]), "r"(b0), "r"(b1),
          "f"(cx), "f"(cy));
}

// scaled softplus core: w = log2(1 + 2^u); scales folded into W1/b1 and W2.
__device__ __forceinline__ float sspc(float u) {
    float t, w;
    asm("ex2.approx.f32 %0, %1;" : "=f"(t) : "f"(u));
    asm("lg2.approx.f32 %0, %1;" : "=f"(w) : "f"(1.0f + t));
    return w;
}

__device__ __forceinline__ void red2(float* p, float a, float b) {
    asm volatile("red.global.add.v2.f32 [%0], {%1,%2};"
                 :: "l"(p), "f"(a), "f"(b) : "memory");
}

__device__ __forceinline__ void cp16(const float* s, const void* g) {
    uint32_t sa;
    asm("{.reg .u64 t; cvta.to.shared.u64 t, %1; cvt.u32.u64 %0, t;}" : "=r"(sa) : "l"(s));
    asm volatile("cp.async.cg.shared.global [%0], [%1], 16;" :: "r"(sa), "l"(g));
}

__global__ void __launch_bounds__(THREADS, 2)
cfconv_kernel(const float* __restrict__ nw,
              const float* __restrict__ rbf,
              const float* __restrict__ W1,
              const float* __restrict__ b1,
              const float* __restrict__ W2,
              const float* __restrict__ b2,
              const int*   __restrict__ src,
              const int*   __restrict__ dst,
              float* __restrict__ out,
              int E) {
    extern __shared__ __align__(16) float sm[];
    float* SBUF = sm + SBUF_OFF;
    uint4* W1F  = (uint4*)(sm + W1F_OFF);
    uint4* W2F  = (uint4*)(sm + W2F_OFF);
    float* B1S  = sm + B1_OFF;
    float* B2S  = sm + B2_OFF;

    const int tid  = threadIdx.x;
    const int warp = tid >> 5;
    const int lane = tid & 31;
    const int r = lane >> 2, c = lane & 3;
    const int wb = warp * 32;

    // ---- one-time: pack W1*K_IN, W2*K_OUT as fp16 B-fragments ----
    for (int idx = tid; idx < 512; idx += THREADS) {
        int g = idx >> 5, ln = idx & 31;
        int s = g >> 2, jp = g & 3;
        int rr = ln >> 2, cc = ln & 3;
        int k0 = s * 16 + 2 * cc;
        int n0 = jp * 16 + rr;
        {
            uint4 v;
            v.x = h2(K_IN * W1[k0 * 64 + n0],       K_IN * W1[(k0 + 1) * 64 + n0]);
            v.y = h2(K_IN * W1[(k0 + 8) * 64 + n0], K_IN * W1[(k0 + 9) * 64 + n0]);
            v.z = h2(K_IN * W1[k0 * 64 + n0 + 8],       K_IN * W1[(k0 + 1) * 64 + n0 + 8]);
            v.w = h2(K_IN * W1[(k0 + 8) * 64 + n0 + 8], K_IN * W1[(k0 + 9) * 64 + n0 + 8]);
            W1F[idx] = v;
        }
        {
            uint4 v;
            v.x = h2(K_OUT * W2[k0 * 64 + n0],       K_OUT * W2[(k0 + 1) * 64 + n0]);
            v.y = h2(K_OUT * W2[(k0 + 8) * 64 + n0], K_OUT * W2[(k0 + 9) * 64 + n0]);
            v.z = h2(K_OUT * W2[k0 * 64 + n0 + 8],       K_OUT * W2[(k0 + 1) * 64 + n0 + 8]);
            v.w = h2(K_OUT * W2[(k0 + 8) * 64 + n0 + 8], K_OUT * W2[(k0 + 9) * 64 + n0 + 8]);
            W2F[idx] = v;
        }
    }
    if (tid < 64) { B1S[tid] = K_IN * b1[tid]; B2S[tid] = b2[tid]; }
    __syncthreads();

    const int ntiles = (E + TILE - 1) / TILE;
    float* wsbuf = SBUF + wb * STRIDE;
    // filter transpose buffer: fp16x2 words, row stride 36 words (144B) ->
    // overlays wsbuf floats [0, 1152) == rows 0..15 of the staging slice.
    uint32_t* FB32 = (uint32_t*)wsbuf;

    // ---- stage first tile (all 16 chunks) ----
    int t = blockIdx.x;
    if (t < ntiles) {
        const int et = t * TILE + wb;
#pragma unroll
        for (int i = 0; i < 16; i++) {
            int g = lane + i * 32;
            int row = g >> 4, q = g & 15;
            int e = et + row;
            float* d = &wsbuf[row * STRIDE + q * 4];
            if (e < E) cp16(d, rbf + (long)e * 64 + q * 4);
            else       *(float4*)d = make_float4(0.f, 0.f, 0.f, 0.f);
        }
        asm volatile("cp.async.commit_group;" ::: "memory");
    }

    for (; t < ntiles; t += gridDim.x) {
        const int et = t * TILE + wb;

        int myE = et + lane;
        int se = (myE < E) ? __ldg(src + myE) : 0;
        int de = (myE < E) ? __ldg(dst + myE) : 0;

        asm volatile("cp.async.wait_group 0;" ::: "memory");
        __syncwarp();

        // ---- GEMM1: peel s=0 with scaled-b1 C-operand, then s=1..3 ----
        float acc[2][8][4];
        {
            uint32_t a[2][4];
#pragma unroll
            for (int mt = 0; mt < 2; mt++) {
                const float* base = wsbuf + (mt * 16 + r) * STRIDE + 2 * c;
                a[mt][0] = h2f2(*(const float2*)(base));
                a[mt][1] = h2f2(*(const float2*)(base + 8 * STRIDE));
                a[mt][2] = h2f2(*(const float2*)(base + 8));
                a[mt][3] = h2f2(*(const float2*)(base + 8 * STRIDE + 8));
            }
#pragma unroll
            for (int jp = 0; jp < 4; jp++) {
                uint4 bv = W1F[jp * 32 + lane];
                float2 bbA = *(const float2*)&B1S[(2 * jp) * 8 + 2 * c];
                float2 bbB = *(const float2*)&B1S[(2 * jp + 1) * 8 + 2 * c];
                mma16c(acc[0][2 * jp],     a[0], bv.x, bv.y, bbA.x, bbA.y);
                mma16c(acc[1][2 * jp],     a[1], bv.x, bv.y, bbA.x, bbA.y);
                mma16c(acc[0][2 * jp + 1], a[0], bv.z, bv.w, bbB.x, bbB.y);
                mma16c(acc[1][2 * jp + 1], a[1], bv.z, bv.w, bbB.x, bbB.y);
            }
        }
#pragma unroll
        for (int s = 1; s < 4; s++) {
            uint32_t a[2][4];
#pragma unroll
            for (int mt = 0; mt < 2; mt++) {
                const float* base = wsbuf + (mt * 16 + r) * STRIDE + s * 16 + 2 * c;
                a[mt][0] = h2f2(*(const float2*)(base));
                a[mt][1] = h2f2(*(const float2*)(base + 8 * STRIDE));
                a[mt][2] = h2f2(*(const float2*)(base + 8));
                a[mt][3] = h2f2(*(const float2*)(base + 8 * STRIDE + 8));
            }
#pragma unroll
            for (int jp = 0; jp < 4; jp++) {
                uint4 bv = W1F[(s * 4 + jp) * 32 + lane];
                mma16(acc[0][2 * jp],     a[0], bv.x, bv.y);
                mma16(acc[1][2 * jp],     a[1], bv.x, bv.y);
                mma16(acc[0][2 * jp + 1], a[0], bv.z, bv.w);
                mma16(acc[1][2 * jp + 1], a[1], bv.z, bv.w);
            }
        }
        __syncwarp();   // warp done reading its SBUF slice

        // ---- hidden = sspc(acc) -> register A-fragments for GEMM2 ----
        uint32_t hp[2][4][4];
#pragma unroll
        for (int mt = 0; mt < 2; mt++) {
#pragma unroll
            for (int j = 0; j < 8; j++) {
                uint32_t h01 = h2(sspc(acc[mt][j][0]), sspc(acc[mt][j][1]));
                uint32_t h23 = h2(sspc(acc[mt][j][2]), sspc(acc[mt][j][3]));
                hp[mt][j >> 1][(j & 1) * 2 + 0] = h01;
                hp[mt][j >> 1][(j & 1) * 2 + 1] = h23;
            }
        }

        // ---- GEMM2: peel s=0 with b2 C-operand, then s=1..3 ----
        {
#pragma unroll
            for (int jp = 0; jp < 4; jp++) {
                uint4 bv = W2F[jp * 32 + lane];
                float2 bbA = *(const float2*)&B2S[(2 * jp) * 8 + 2 * c];
                float2 bbB = *(const float2*)&B2S[(2 * jp + 1) * 8 + 2 * c];
                mma16c(acc[0][2 * jp],     hp[0][0], bv.x, bv.y, bbA.x, bbA.y);
                mma16c(acc[1][2 * jp],     hp[1][0], bv.x, bv.y, bbA.x, bbA.y);
                mma16c(acc[0][2 * jp + 1], hp[0][0], bv.z, bv.w, bbB.x, bbB.y);
                mma16c(acc[1][2 * jp + 1], hp[1][0], bv.z, bv.w, bbB.x, bbB.y);
            }
        }
#pragma unroll
        for (int s = 1; s < 4; s++) {
#pragma unroll
            for (int jp = 0; jp < 4; jp++) {
                uint4 bv = W2F[(s * 4 + jp) * 32 + lane];
                mma16(acc[0][2 * jp],     hp[0][s], bv.x, bv.y);
                mma16(acc[1][2 * jp],     hp[1][s], bv.x, bv.y);
                mma16(acc[0][2 * jp + 1], hp[0][s], bv.z, bv.w);
                mma16(acc[1][2 * jp + 1], hp[1][s], bv.z, bv.w);
            }
        }

        // ---- filter -> fp16 transpose buffer (conflict-free STS.32) ----
        // word (row x, pair w) at FB32[x*36 + w], w = 4j + c holds cols 2w,2w+1
#pragma unroll
        for (int mt = 0; mt < 2; mt++) {
#pragma unroll
            for (int rr = 0; rr < 2; rr++) {
                int x = mt * 16 + rr * 8 + r;
                uint32_t* rowp = FB32 + x * 36 + c;
#pragma unroll
                for (int j = 0; j < 8; j++)
                    rowp[4 * j] = h2(acc[mt][j][rr * 2 + 0], acc[mt][j][rr * 2 + 1]);
            }
        }
        __syncwarp();   // cross-lane FB visibility

        // ---- prefetch NEXT tile rows 16..31 (disjoint from FB32) ----
        int tn = t + gridDim.x;
        if (tn < ntiles) {
            const int etn = tn * TILE + wb;
#pragma unroll
            for (int i = 8; i < 16; i++) {
                int g = lane + i * 32;
                int row = g >> 4, q = g & 15;
                int e = etn + row;
                float* d = &wsbuf[row * STRIDE + q * 4];
                if (e < E) cp16(d, rbf + (long)e * 64 + q * 4);
                else       *(float4*)d = make_float4(0.f, 0.f, 0.f, 0.f);
            }
            asm volatile("cp.async.commit_group;" ::: "memory");
        }

        // ---- per-edge coalesced epilogue: lane l owns cols 2l,2l+1 ----
#pragma unroll 8
        for (int e = 0; e < 32; e++) {
            int sN = __shfl_sync(0xffffffff, se, e);
            int dN = __shfl_sync(0xffffffff, de, e);
            if (et + e < E) {
                uint32_t fv = FB32[e * 36 + lane];
                float2 f = __half22float2(*(const __half2*)&fv);
                float2 nv = __ldg((const float2*)(nw + (long)sN * 64 + 2 * lane));
                red2(out + (long)dN * 64 + 2 * lane, f.x * nv.x, f.y * nv.y);
            }
        }

        // ---- prefetch NEXT tile rows 0..15 (reclaims FB32 region) ----
        if (tn < ntiles) {
            const int etn = tn * TILE + wb;
#pragma unroll
            for (int i = 0; i < 8; i++) {
                int g = lane + i * 32;
                int row = g >> 4, q = g & 15;
                int e = etn + row;
                float* d = &wsbuf[row * STRIDE + q * 4];
                if (e < E) cp16(d, rbf + (long)e * 64 + q * 4);
                else       *(float4*)d = make_float4(0.f, 0.f, 0.f, 0.f);
            }
            asm volatile("cp.async.commit_group;" ::: "memory");
        }
    }
}

__global__ void zero_kernel(float4* __restrict__ o, int n4) {
    int i = blockIdx.x * blockDim.x + threadIdx.x;
    if (i < n4) o[i] = make_float4(0.f, 0.f, 0.f, 0.f);
}

extern "C" void kernel_launch(void* const* d_in, const int* in_sizes, int n_in,
                              void* d_out, int out_size) {
    const float* nw  = (const float*)d_in[0];
    const float* rbf = (const float*)d_in[1];
    const float* W1  = (const float*)d_in[2];
    const float* b1  = (const float*)d_in[3];
    const float* W2  = (const float*)d_in[4];
    const float* b2  = (const float*)d_in[5];
    const int*   src = (const int*)d_in[6];
    const int*   dst = (const int*)d_in[7];
    float* out = (float*)d_out;

    const int E = in_sizes[1] / 64;

    cudaFuncSetAttribute(cfconv_kernel,
                         cudaFuncAttributeMaxDynamicSharedMemorySize, SMEM_BYTES);

    int n4 = out_size / 4;
    zero_kernel<<<(n4 + 255) / 256, 256>>>((float4*)out, n4);

    cfconv_kernel<<<304, THREADS, SMEM_BYTES>>>(nw, rbf, W1, b1, W2, b2, src, dst, out, E);
}

// round 15
// speedup vs baseline: 1.0001x; 1.0001x over previous
#include <cuda_runtime.h>
#include <cuda_fp16.h>
#include <cstdint>

// CFConv fused via mma.sync fp16 (m16n8k16, fp32 accum). Warp-autonomous
// 32-edge slices; hidden passed GEMM1 -> GEMM2 in registers; biases via mma
// C-operands; softplus constants folded into W1/b1 and W2. Epilogue routes
// the filter through a DEDICATED fp16 smem transpose buffer (16 edges at a
// time, two passes) so nw gather / out scatter are per-edge coalesced while
// the full next-tile prefetch still issues before the epilogue.
// out[dst] += nw[src] * ( ssp(rbf @ W1 + b1) @ W2 + b2 )

static constexpr int TILE    = 256;
static constexpr int THREADS = 256;
static constexpr int STRIDE  = 72;    // fp32 row stride (conflict-free LDS.64)

// shared layout (floats)
static constexpr int SBUF_OFF = 0;                    // 256 x 72 fp32
static constexpr int W1F_OFF  = TILE * STRIDE;        // 18432: 512 uint4 fp16 frags
static constexpr int W2F_OFF  = W1F_OFF + 2048;       // 20480
static constexpr int B1_OFF   = W2F_OFF + 2048;       // 22528
static constexpr int B2_OFF   = B1_OFF + 64;          // 22592
static constexpr int FB_OFF   = B2_OFF + 64;          // 22656: 8 warps x 16x36 words
static constexpr int SMEM_FLOATS = FB_OFF + 8 * 16 * 36;   // 27264
static constexpr int SMEM_BYTES  = SMEM_FLOATS * 4;        // 109056

static constexpr float K_IN  = 0.72134752f;   // 1/(2 ln 2)
static constexpr float K_OUT = 1.38629436f;   // 2 ln 2

__device__ __forceinline__ uint32_t h2(float lo, float hi) {
    uint32_t d;   // first PTX src -> upper half
    asm("cvt.rn.f16x2.f32 %0, %1, %2;" : "=r"(d) : "f"(hi), "f"(lo));
    return d;
}
__device__ __forceinline__ uint32_t h2f2(float2 p) { return h2(p.x, p.y); }

__device__ __forceinline__ void mma16(float c[4], const uint32_t a[4],
                                      uint32_t b0, uint32_t b1) {
    asm volatile(
        "mma.sync.aligned.m16n8k16.row.col.f32.f16.f16.f32 "
        "{%0,%1,%2,%3}, {%4,%5,%6,%7}, {%8,%9}, {%0,%1,%2,%3};"
        : "+f"(c[0]), "+f"(c[1]), "+f"(c[2]), "+f"(c[3])
        : "r"(a[0]), "r"(a[1]), "r"(a[2]), "r"(a[3]), "r"(b0), "r"(b1));
}

// first K-step: D = A*B + {cx,cy,cx,cy}  (bias injected via C operand)
__device__ __forceinline__ void mma16c(float d[4], const uint32_t a[4],
                                       uint32_t b0, uint32_t b1,
                                       float cx, float cy) {
    asm volatile(
        "mma.sync.aligned.m16n8k16.row.col.f32.f16.f16.f32 "
        "{%0,%1,%2,%3}, {%4,%5,%6,%7}, {%8,%9}, {%10,%11,%10,%11};"
        : "=f"(d[0]), "=f"(d[1]), "=f"(d[2]), "=f"(d[3])
        : "r"(a[0]), "r"(a[1]), "r"(a[2]), "r"(a[3]), "r"(b0), "r"(b1),
          "f"(cx), "f"(cy));
}

// scaled softplus core: w = log2(1 + 2^u); scales folded into W1/b1 and W2.
__device__ __forceinline__ float sspc(float u) {
    float t, w;
    asm("ex2.approx.f32 %0, %1;" : "=f"(t) : "f"(u));
    asm("lg2.approx.f32 %0, %1;" : "=f"(w) : "f"(1.0f + t));
    return w;
}

__device__ __forceinline__ void red2(float* p, float a, float b) {
    asm volatile("red.global.add.v2.f32 [%0], {%1,%2};"
                 :: "l"(p), "f"(a), "f"(b) : "memory");
}

__device__ __forceinline__ void cp16(const float* s, const void* g) {
    uint32_t sa;
    asm("{.reg .u64 t; cvta.to.shared.u64 t, %1; cvt.u32.u64 %0, t;}" : "=r"(sa) : "l"(s));
    asm volatile("cp.async.cg.shared.global [%0], [%1], 16;" :: "r"(sa), "l"(g));
}

__global__ void __launch_bounds__(THREADS, 2)
cfconv_kernel(const float* __restrict__ nw,
              const float* __restrict__ rbf,
              const float* __restrict__ W1,
              const float* __restrict__ b1,
              const float* __restrict__ W2,
              const float* __restrict__ b2,
              const int*   __restrict__ src,
              const int*   __restrict__ dst,
              float* __restrict__ out,
              int E) {
    extern __shared__ __align__(16) float sm[];
    float* SBUF = sm + SBUF_OFF;
    uint4* W1F  = (uint4*)(sm + W1F_OFF);
    uint4* W2F  = (uint4*)(sm + W2F_OFF);
    float* B1S  = sm + B1_OFF;
    float* B2S  = sm + B2_OFF;

    const int tid  = threadIdx.x;
    const int warp = tid >> 5;
    const int lane = tid & 31;
    const int r = lane >> 2, c = lane & 3;
    const int wb = warp * 32;

    // ---- one-time: pack W1*K_IN, W2*K_OUT as fp16 B-fragments ----
    for (int idx = tid; idx < 512; idx += THREADS) {
        int g = idx >> 5, ln = idx & 31;
        int s = g >> 2, jp = g & 3;
        int rr = ln >> 2, cc = ln & 3;
        int k0 = s * 16 + 2 * cc;
        int n0 = jp * 16 + rr;
        {
            uint4 v;
            v.x = h2(K_IN * W1[k0 * 64 + n0],       K_IN * W1[(k0 + 1) * 64 + n0]);
            v.y = h2(K_IN * W1[(k0 + 8) * 64 + n0], K_IN * W1[(k0 + 9) * 64 + n0]);
            v.z = h2(K_IN * W1[k0 * 64 + n0 + 8],       K_IN * W1[(k0 + 1) * 64 + n0 + 8]);
            v.w = h2(K_IN * W1[(k0 + 8) * 64 + n0 + 8], K_IN * W1[(k0 + 9) * 64 + n0 + 8]);
            W1F[idx] = v;
        }
        {
            uint4 v;
            v.x = h2(K_OUT * W2[k0 * 64 + n0],       K_OUT * W2[(k0 + 1) * 64 + n0]);
            v.y = h2(K_OUT * W2[(k0 + 8) * 64 + n0], K_OUT * W2[(k0 + 9) * 64 + n0]);
            v.z = h2(K_OUT * W2[k0 * 64 + n0 + 8],       K_OUT * W2[(k0 + 1) * 64 + n0 + 8]);
            v.w = h2(K_OUT * W2[(k0 + 8) * 64 + n0 + 8], K_OUT * W2[(k0 + 9) * 64 + n0 + 8]);
            W2F[idx] = v;
        }
    }
    if (tid < 64) { B1S[tid] = K_IN * b1[tid]; B2S[tid] = b2[tid]; }
    __syncthreads();

    const int ntiles = (E + TILE - 1) / TILE;
    float* wsbuf = SBUF + wb * STRIDE;
    uint32_t* FB = (uint32_t*)(sm + FB_OFF) + warp * 16 * 36;  // 16 edges x 36 words

    // ---- stage first tile ----
    int t = blockIdx.x;
    if (t < ntiles) {
        const int et = t * TILE + wb;
#pragma unroll
        for (int i = 0; i < 16; i++) {
            int g = lane + i * 32;
            int row = g >> 4, q = g & 15;
            int e = et + row;
            float* d = &wsbuf[row * STRIDE + q * 4];
            if (e < E) cp16(d, rbf + (long)e * 64 + q * 4);
            else       *(float4*)d = make_float4(0.f, 0.f, 0.f, 0.f);
        }
        asm volatile("cp.async.commit_group;" ::: "memory");
    }

    for (; t < ntiles; t += gridDim.x) {
        const int et = t * TILE + wb;

        int myE = et + lane;
        int se = (myE < E) ? __ldg(src + myE) : 0;
        int de = (myE < E) ? __ldg(dst + myE) : 0;

        asm volatile("cp.async.wait_group 0;" ::: "memory");
        __syncwarp();

        // ---- GEMM1: peel s=0 with scaled-b1 C-operand, then s=1..3 ----
        float acc[2][8][4];
        {
            uint32_t a[2][4];
#pragma unroll
            for (int mt = 0; mt < 2; mt++) {
                const float* base = wsbuf + (mt * 16 + r) * STRIDE + 2 * c;
                a[mt][0] = h2f2(*(const float2*)(base));
                a[mt][1] = h2f2(*(const float2*)(base + 8 * STRIDE));
                a[mt][2] = h2f2(*(const float2*)(base + 8));
                a[mt][3] = h2f2(*(const float2*)(base + 8 * STRIDE + 8));
            }
#pragma unroll
            for (int jp = 0; jp < 4; jp++) {
                uint4 bv = W1F[jp * 32 + lane];
                float2 bbA = *(const float2*)&B1S[(2 * jp) * 8 + 2 * c];
                float2 bbB = *(const float2*)&B1S[(2 * jp + 1) * 8 + 2 * c];
                mma16c(acc[0][2 * jp],     a[0], bv.x, bv.y, bbA.x, bbA.y);
                mma16c(acc[1][2 * jp],     a[1], bv.x, bv.y, bbA.x, bbA.y);
                mma16c(acc[0][2 * jp + 1], a[0], bv.z, bv.w, bbB.x, bbB.y);
                mma16c(acc[1][2 * jp + 1], a[1], bv.z, bv.w, bbB.x, bbB.y);
            }
        }
#pragma unroll
        for (int s = 1; s < 4; s++) {
            uint32_t a[2][4];
#pragma unroll
            for (int mt = 0; mt < 2; mt++) {
                const float* base = wsbuf + (mt * 16 + r) * STRIDE + s * 16 + 2 * c;
                a[mt][0] = h2f2(*(const float2*)(base));
                a[mt][1] = h2f2(*(const float2*)(base + 8 * STRIDE));
                a[mt][2] = h2f2(*(const float2*)(base + 8));
                a[mt][3] = h2f2(*(const float2*)(base + 8 * STRIDE + 8));
            }
#pragma unroll
            for (int jp = 0; jp < 4; jp++) {
                uint4 bv = W1F[(s * 4 + jp) * 32 + lane];
                mma16(acc[0][2 * jp],     a[0], bv.x, bv.y);
                mma16(acc[1][2 * jp],     a[1], bv.x, bv.y);
                mma16(acc[0][2 * jp + 1], a[0], bv.z, bv.w);
                mma16(acc[1][2 * jp + 1], a[1], bv.z, bv.w);
            }
        }
        __syncwarp();   // warp done reading its SBUF slice

        // ---- hidden = sspc(acc) -> register A-fragments for GEMM2 ----
        uint32_t hp[2][4][4];
#pragma unroll
        for (int mt = 0; mt < 2; mt++) {
#pragma unroll
            for (int j = 0; j < 8; j++) {
                uint32_t h01 = h2(sspc(acc[mt][j][0]), sspc(acc[mt][j][1]));
                uint32_t h23 = h2(sspc(acc[mt][j][2]), sspc(acc[mt][j][3]));
                hp[mt][j >> 1][(j & 1) * 2 + 0] = h01;
                hp[mt][j >> 1][(j & 1) * 2 + 1] = h23;
            }
        }

        // ---- SBUF slice free: stage NEXT tile (full 16 chunks, hides behind
        //      GEMM2 + epilogue) ----
        int tn = t + gridDim.x;
        if (tn < ntiles) {
            const int etn = tn * TILE + wb;
#pragma unroll
            for (int i = 0; i < 16; i++) {
                int g = lane + i * 32;
                int row = g >> 4, q = g & 15;
                int e = etn + row;
                float* d = &wsbuf[row * STRIDE + q * 4];
                if (e < E) cp16(d, rbf + (long)e * 64 + q * 4);
                else       *(float4*)d = make_float4(0.f, 0.f, 0.f, 0.f);
            }
            asm volatile("cp.async.commit_group;" ::: "memory");
        }

        // ---- GEMM2: peel s=0 with b2 C-operand, then s=1..3 ----
        {
#pragma unroll
            for (int jp = 0; jp < 4; jp++) {
                uint4 bv = W2F[jp * 32 + lane];
                float2 bbA = *(const float2*)&B2S[(2 * jp) * 8 + 2 * c];
                float2 bbB = *(const float2*)&B2S[(2 * jp + 1) * 8 + 2 * c];
                mma16c(acc[0][2 * jp],     hp[0][0], bv.x, bv.y, bbA.x, bbA.y);
                mma16c(acc[1][2 * jp],     hp[1][0], bv.x, bv.y, bbA.x, bbA.y);
                mma16c(acc[0][2 * jp + 1], hp[0][0], bv.z, bv.w, bbB.x, bbB.y);
                mma16c(acc[1][2 * jp + 1], hp[1][0], bv.z, bv.w, bbB.x, bbB.y);
            }
        }
#pragma unroll
        for (int s = 1; s < 4; s++) {
#pragma unroll
            for (int jp = 0; jp < 4; jp++) {
                uint4 bv = W2F[(s * 4 + jp) * 32 + lane];
                mma16(acc[0][2 * jp],     hp[0][s], bv.x, bv.y);
                mma16(acc[1][2 * jp],     hp[1][s], bv.x, bv.y);
                mma16(acc[0][2 * jp + 1], hp[0][s], bv.z, bv.w);
                mma16(acc[1][2 * jp + 1], hp[1][s], bv.z, bv.w);
            }
        }

        // ---- epilogue: two 16-edge passes through the FB transpose buffer ----
#pragma unroll
        for (int mt = 0; mt < 2; mt++) {
            // write: FB[(rr*8+r)*36 + 4j+c] = cols {8j+2c, 8j+2c+1} of edge row
#pragma unroll
            for (int rr = 0; rr < 2; rr++) {
                uint32_t* rowp = FB + (rr * 8 + r) * 36 + c;
#pragma unroll
                for (int j = 0; j < 8; j++)
                    rowp[4 * j] = h2(acc[mt][j][rr * 2 + 0], acc[mt][j][rr * 2 + 1]);
            }
            __syncwarp();

            // read: per edge, lane l owns cols 2l,2l+1 (coalesced LDG/RED)
#pragma unroll 8
            for (int e = 0; e < 16; e++) {
                int x = mt * 16 + e;
                int sN = __shfl_sync(0xffffffff, se, x);
                int dN = __shfl_sync(0xffffffff, de, x);
                if (et + x < E) {
                    uint32_t fv = FB[e * 36 + lane];
                    float2 f = __half22float2(*(const __half2*)&fv);
                    float2 nv = __ldg((const float2*)(nw + (long)sN * 64 + 2 * lane));
                    red2(out + (long)dN * 64 + 2 * lane, f.x * nv.x, f.y * nv.y);
                }
            }
            __syncwarp();
        }
    }
}

__global__ void zero_kernel(float4* __restrict__ o, int n4) {
    int i = blockIdx.x * blockDim.x + threadIdx.x;
    if (i < n4) o[i] = make_float4(0.f, 0.f, 0.f, 0.f);
}

extern "C" void kernel_launch(void* const* d_in, const int* in_sizes, int n_in,
                              void* d_out, int out_size) {
    const float* nw  = (const float*)d_in[0];
    const float* rbf = (const float*)d_in[1];
    const float* W1  = (const float*)d_in[2];
    const float* b1  = (const float*)d_in[3];
    const float* W2  = (const float*)d_in[4];
    const float* b2  = (const float*)d_in[5];
    const int*   src = (const int*)d_in[6];
    const int*   dst = (const int*)d_in[7];
    float* out = (float*)d_out;

    const int E = in_sizes[1] / 64;

    cudaFuncSetAttribute(cfconv_kernel,
                         cudaFuncAttributeMaxDynamicSharedMemorySize, SMEM_BYTES);

    int n4 = out_size / 4;
    zero_kernel<<<(n4 + 255) / 256, 256>>>((float4*)out, n4);

    cfconv_kernel<<<304, THREADS, SMEM_BYTES>>>(nw, rbf, W1, b1, W2, b2, src, dst, out, E);
}

// round 16
// speedup vs baseline: 1.6956x; 1.6954x over previous
#include <cuda_runtime.h>
#include <cuda_fp16.h>
#include <cstdint>

// CFConv fused via mma.sync fp16 (m16n8k16, fp32 accum). Warp-autonomous
// 32-edge slices; hidden passed GEMM1 -> GEMM2 in registers; biases via mma
// C-operands; softplus folded into W1/b1,W2. Coalesced epilogue through a
// dedicated fp16 smem transpose buffer, with a BRANCHLESS batched read pass
// (8 LDGs in flight before any RED) so the L2 latency is pipelined.
// out[dst] += nw[src] * ( ssp(rbf @ W1 + b1) @ W2 + b2 )

static constexpr int TILE    = 256;
static constexpr int THREADS = 256;
static constexpr int STRIDE  = 72;

// shared layout (floats)
static constexpr int SBUF_OFF = 0;                    // 256 x 72 fp32
static constexpr int W1F_OFF  = TILE * STRIDE;        // 18432
static constexpr int W2F_OFF  = W1F_OFF + 2048;       // 20480
static constexpr int B1_OFF   = W2F_OFF + 2048;       // 22528
static constexpr int B2_OFF   = B1_OFF + 64;          // 22592
static constexpr int FB_OFF   = B2_OFF + 64;          // 22656: 8 warps x 16x36 words
static constexpr int SMEM_FLOATS = FB_OFF + 8 * 16 * 36;   // 27264
static constexpr int SMEM_BYTES  = SMEM_FLOATS * 4;        // 109056

static constexpr float K_IN  = 0.72134752f;   // 1/(2 ln 2)
static constexpr float K_OUT = 1.38629436f;   // 2 ln 2

__device__ __forceinline__ uint32_t h2(float lo, float hi) {
    uint32_t d;
    asm("cvt.rn.f16x2.f32 %0, %1, %2;" : "=r"(d) : "f"(hi), "f"(lo));
    return d;
}
__device__ __forceinline__ uint32_t h2f2(float2 p) { return h2(p.x, p.y); }

__device__ __forceinline__ void mma16(float c[4], const uint32_t a[4],
                                      uint32_t b0, uint32_t b1) {
    asm volatile(
        "mma.sync.aligned.m16n8k16.row.col.f32.f16.f16.f32 "
        "{%0,%1,%2,%3}, {%4,%5,%6,%7}, {%8,%9}, {%0,%1,%2,%3};"
        : "+f"(c[0]), "+f"(c[1]), "+f"(c[2]), "+f"(c[3])
        : "r"(a[0]), "r"(a[1]), "r"(a[2]), "r"(a[3]), "r"(b0), "r"(b1));
}

__device__ __forceinline__ void mma16c(float d[4], const uint32_t a[4],
                                       uint32_t b0, uint32_t b1,
                                       float cx, float cy) {
    asm volatile(
        "mma.sync.aligned.m16n8k16.row.col.f32.f16.f16.f32 "
        "{%0,%1,%2,%3}, {%4,%5,%6,%7}, {%8,%9}, {%10,%11,%10,%11};"
        : "=f"(d[0]), "=f"(d[1]), "=f"(d[2]), "=f"(d[3])
        : "r"(a[0]), "r"(a[1]), "r"(a[2]), "r"(a[3]), "r"(b0), "r"(b1),
          "f"(cx), "f"(cy));
}

__device__ __forceinline__ float sspc(float u) {
    float t, w;
    asm("ex2.approx.f32 %0, %1;" : "=f"(t) : "f"(u));
    asm("lg2.approx.f32 %0, %1;" : "=f"(w) : "f"(1.0f + t));
    return w;
}

__device__ __forceinline__ void red2(float* p, float a, float b) {
    asm volatile("red.global.add.v2.f32 [%0], {%1,%2};"
                 :: "l"(p), "f"(a), "f"(b) : "memory");
}

// predicated red.v2 (no branch -> no BSSY/BSYNC)
__device__ __forceinline__ void red2p(float* p, float a, float b, int ok) {
    asm volatile("{.reg .pred q; setp.ne.s32 q, %3, 0;\n"
                 "@q red.global.add.v2.f32 [%0], {%1,%2};}"
                 :: "l"(p), "f"(a), "f"(b), "r"(ok) : "memory");
}

__device__ __forceinline__ void cp16(const float* s, const void* g) {
    uint32_t sa;
    asm("{.reg .u64 t; cvta.to.shared.u64 t, %1; cvt.u32.u64 %0, t;}" : "=r"(sa) : "l"(s));
    asm volatile("cp.async.cg.shared.global [%0], [%1], 16;" :: "r"(sa), "l"(g));
}

__global__ void __launch_bounds__(THREADS, 2)
cfconv_kernel(const float* __restrict__ nw,
              const float* __restrict__ rbf,
              const float* __restrict__ W1,
              const float* __restrict__ b1,
              const float* __restrict__ W2,
              const float* __restrict__ b2,
              const int*   __restrict__ src,
              const int*   __restrict__ dst,
              float* __restrict__ out,
              int E) {
    extern __shared__ __align__(16) float sm[];
    float* SBUF = sm + SBUF_OFF;
    uint4* W1F  = (uint4*)(sm + W1F_OFF);
    uint4* W2F  = (uint4*)(sm + W2F_OFF);
    float* B1S  = sm + B1_OFF;
    float* B2S  = sm + B2_OFF;

    const int tid  = threadIdx.x;
    const int warp = tid >> 5;
    const int lane = tid & 31;
    const int r = lane >> 2, c = lane & 3;
    const int wb = warp * 32;

    // ---- one-time: pack W1*K_IN, W2*K_OUT as fp16 B-fragments ----
    for (int idx = tid; idx < 512; idx += THREADS) {
        int g = idx >> 5, ln = idx & 31;
        int s = g >> 2, jp = g & 3;
        int rr = ln >> 2, cc = ln & 3;
        int k0 = s * 16 + 2 * cc;
        int n0 = jp * 16 + rr;
        {
            uint4 v;
            v.x = h2(K_IN * W1[k0 * 64 + n0],       K_IN * W1[(k0 + 1) * 64 + n0]);
            v.y = h2(K_IN * W1[(k0 + 8) * 64 + n0], K_IN * W1[(k0 + 9) * 64 + n0]);
            v.z = h2(K_IN * W1[k0 * 64 + n0 + 8],       K_IN * W1[(k0 + 1) * 64 + n0 + 8]);
            v.w = h2(K_IN * W1[(k0 + 8) * 64 + n0 + 8], K_IN * W1[(k0 + 9) * 64 + n0 + 8]);
            W1F[idx] = v;
        }
        {
            uint4 v;
            v.x = h2(K_OUT * W2[k0 * 64 + n0],       K_OUT * W2[(k0 + 1) * 64 + n0]);
            v.y = h2(K_OUT * W2[(k0 + 8) * 64 + n0], K_OUT * W2[(k0 + 9) * 64 + n0]);
            v.z = h2(K_OUT * W2[k0 * 64 + n0 + 8],       K_OUT * W2[(k0 + 1) * 64 + n0 + 8]);
            v.w = h2(K_OUT * W2[(k0 + 8) * 64 + n0 + 8], K_OUT * W2[(k0 + 9) * 64 + n0 + 8]);
            W2F[idx] = v;
        }
    }
    if (tid < 64) { B1S[tid] = K_IN * b1[tid]; B2S[tid] = b2[tid]; }
    __syncthreads();

    const int ntiles = (E + TILE - 1) / TILE;
    float* wsbuf = SBUF + wb * STRIDE;
    uint32_t* FB = (uint32_t*)(sm + FB_OFF) + warp * 16 * 36;

    // ---- stage first tile ----
    int t = blockIdx.x;
    if (t < ntiles) {
        const int et = t * TILE + wb;
#pragma unroll
        for (int i = 0; i < 16; i++) {
            int g = lane + i * 32;
            int row = g >> 4, q = g & 15;
            int e = et + row;
            float* d = &wsbuf[row * STRIDE + q * 4];
            if (e < E) cp16(d, rbf + (long)e * 64 + q * 4);
            else       *(float4*)d = make_float4(0.f, 0.f, 0.f, 0.f);
        }
        asm volatile("cp.async.commit_group;" ::: "memory");
    }

    for (; t < ntiles; t += gridDim.x) {
        const int et = t * TILE + wb;

        int myE = et + lane;
        int se = (myE < E) ? __ldg(src + myE) : 0;
        int de = (myE < E) ? __ldg(dst + myE) : 0;

        asm volatile("cp.async.wait_group 0;" ::: "memory");
        __syncwarp();

        // ---- GEMM1: peel s=0 with scaled-b1 C-operand, then s=1..3 ----
        float acc[2][8][4];
        {
            uint32_t a[2][4];
#pragma unroll
            for (int mt = 0; mt < 2; mt++) {
                const float* base = wsbuf + (mt * 16 + r) * STRIDE + 2 * c;
                a[mt][0] = h2f2(*(const float2*)(base));
                a[mt][1] = h2f2(*(const float2*)(base + 8 * STRIDE));
                a[mt][2] = h2f2(*(const float2*)(base + 8));
                a[mt][3] = h2f2(*(const float2*)(base + 8 * STRIDE + 8));
            }
#pragma unroll
            for (int jp = 0; jp < 4; jp++) {
                uint4 bv = W1F[jp * 32 + lane];
                float2 bbA = *(const float2*)&B1S[(2 * jp) * 8 + 2 * c];
                float2 bbB = *(const float2*)&B1S[(2 * jp + 1) * 8 + 2 * c];
                mma16c(acc[0][2 * jp],     a[0], bv.x, bv.y, bbA.x, bbA.y);
                mma16c(acc[1][2 * jp],     a[1], bv.x, bv.y, bbA.x, bbA.y);
                mma16c(acc[0][2 * jp + 1], a[0], bv.z, bv.w, bbB.x, bbB.y);
                mma16c(acc[1][2 * jp + 1], a[1], bv.z, bv.w, bbB.x, bbB.y);
            }
        }
#pragma unroll
        for (int s = 1; s < 4; s++) {
            uint32_t a[2][4];
#pragma unroll
            for (int mt = 0; mt < 2; mt++) {
                const float* base = wsbuf + (mt * 16 + r) * STRIDE + s * 16 + 2 * c;
                a[mt][0] = h2f2(*(const float2*)(base));
                a[mt][1] = h2f2(*(const float2*)(base + 8 * STRIDE));
                a[mt][2] = h2f2(*(const float2*)(base + 8));
                a[mt][3] = h2f2(*(const float2*)(base + 8 * STRIDE + 8));
            }
#pragma unroll
            for (int jp = 0; jp < 4; jp++) {
                uint4 bv = W1F[(s * 4 + jp) * 32 + lane];
                mma16(acc[0][2 * jp],     a[0], bv.x, bv.y);
                mma16(acc[1][2 * jp],     a[1], bv.x, bv.y);
                mma16(acc[0][2 * jp + 1], a[0], bv.z, bv.w);
                mma16(acc[1][2 * jp + 1], a[1], bv.z, bv.w);
            }
        }
        __syncwarp();

        // ---- hidden = sspc(acc) -> register A-fragments for GEMM2 ----
        uint32_t hp[2][4][4];
#pragma unroll
        for (int mt = 0; mt < 2; mt++) {
#pragma unroll
            for (int j = 0; j < 8; j++) {
                uint32_t h01 = h2(sspc(acc[mt][j][0]), sspc(acc[mt][j][1]));
                uint32_t h23 = h2(sspc(acc[mt][j][2]), sspc(acc[mt][j][3]));
                hp[mt][j >> 1][(j & 1) * 2 + 0] = h01;
                hp[mt][j >> 1][(j & 1) * 2 + 1] = h23;
            }
        }

        // ---- SBUF slice free: stage NEXT tile ----
        int tn = t + gridDim.x;
        if (tn < ntiles) {
            const int etn = tn * TILE + wb;
#pragma unroll
            for (int i = 0; i < 16; i++) {
                int g = lane + i * 32;
                int row = g >> 4, q = g & 15;
                int e = etn + row;
                float* d = &wsbuf[row * STRIDE + q * 4];
                if (e < E) cp16(d, rbf + (long)e * 64 + q * 4);
                else       *(float4*)d = make_float4(0.f, 0.f, 0.f, 0.f);
            }
            asm volatile("cp.async.commit_group;" ::: "memory");
        }

        // ---- GEMM2: peel s=0 with b2 C-operand, then s=1..3 ----
        {
#pragma unroll
            for (int jp = 0; jp < 4; jp++) {
                uint4 bv = W2F[jp * 32 + lane];
                float2 bbA = *(const float2*)&B2S[(2 * jp) * 8 + 2 * c];
                float2 bbB = *(const float2*)&B2S[(2 * jp + 1) * 8 + 2 * c];
                mma16c(acc[0][2 * jp],     hp[0][0], bv.x, bv.y, bbA.x, bbA.y);
                mma16c(acc[1][2 * jp],     hp[1][0], bv.x, bv.y, bbA.x, bbA.y);
                mma16c(acc[0][2 * jp + 1], hp[0][0], bv.z, bv.w, bbB.x, bbB.y);
                mma16c(acc[1][2 * jp + 1], hp[1][0], bv.z, bv.w, bbB.x, bbB.y);
            }
        }
#pragma unroll
        for (int s = 1; s < 4; s++) {
#pragma unroll
            for (int jp = 0; jp < 4; jp++) {
                uint4 bv = W2F[(s * 4 + jp) * 32 + lane];
                mma16(acc[0][2 * jp],     hp[0][s], bv.x, bv.y);
                mma16(acc[1][2 * jp],     hp[1][s], bv.x, bv.y);
                mma16(acc[0][2 * jp + 1], hp[0][s], bv.z, bv.w);
                mma16(acc[1][2 * jp + 1], hp[1][s], bv.z, bv.w);
            }
        }

        // ---- epilogue: two 16-edge passes; batched branchless read ----
        const bool full = (et + 32 <= E);
#pragma unroll
        for (int mt = 0; mt < 2; mt++) {
            // write FB (conflict-free STS.32)
#pragma unroll
            for (int rr = 0; rr < 2; rr++) {
                uint32_t* rowp = FB + (rr * 8 + r) * 36 + c;
#pragma unroll
                for (int j = 0; j < 8; j++)
                    rowp[4 * j] = h2(acc[mt][j][rr * 2 + 0], acc[mt][j][rr * 2 + 1]);
            }
            __syncwarp();

            if (full) {
                // branchless: 2 batches of 8 edges, all LDGs issued first
#pragma unroll
                for (int hf = 0; hf < 2; hf++) {
                    uint32_t fv[8]; float2 nv[8]; long dn[8];
#pragma unroll
                    for (int e = 0; e < 8; e++) {
                        int x = mt * 16 + hf * 8 + e;
                        int sN = __shfl_sync(0xffffffff, se, x);
                        dn[e] = (long)__shfl_sync(0xffffffff, de, x);
                        fv[e] = FB[(hf * 8 + e) * 36 + lane];
                        nv[e] = __ldg((const float2*)(nw + (long)sN * 64 + 2 * lane));
                    }
#pragma unroll
                    for (int e = 0; e < 8; e++) {
                        float2 f = __half22float2(*(const __half2*)&fv[e]);
                        red2(out + dn[e] * 64 + 2 * lane, f.x * nv[e].x, f.y * nv[e].y);
                    }
                }
            } else {
                // tail tile: predicated, still branchless inner
#pragma unroll
                for (int e = 0; e < 16; e++) {
                    int x = mt * 16 + e;
                    int sN = __shfl_sync(0xffffffff, se, x);
                    int dN = __shfl_sync(0xffffffff, de, x);
                    uint32_t fv = FB[e * 36 + lane];
                    float2 f = __half22float2(*(const __half2*)&fv);
                    float2 nv = __ldg((const float2*)(nw + (long)sN * 64 + 2 * lane));
                    red2p(out + (long)dN * 64 + 2 * lane,
                          f.x * nv.x, f.y * nv.y, (et + x < E) ? 1 : 0);
                }
            }
            __syncwarp();
        }
    }
}

__global__ void zero_kernel(float4* __restrict__ o, int n4) {
    int i = blockIdx.x * blockDim.x + threadIdx.x;
    if (i < n4) o[i] = make_float4(0.f, 0.f, 0.f, 0.f);
}

extern "C" void kernel_launch(void* const* d_in, const int* in_sizes, int n_in,
                              void* d_out, int out_size) {
    const float* nw  = (const float*)d_in[0];
    const float* rbf = (const float*)d_in[1];
    const float* W1  = (const float*)d_in[2];
    const float* b1  = (const float*)d_in[3];
    const float* W2  = (const float*)d_in[4];
    const float* b2  = (const float*)d_in[5];
    const int*   src = (const int*)d_in[6];
    const int*   dst = (const int*)d_in[7];
    float* out = (float*)d_out;

    const int E = in_sizes[1] / 64;

    cudaFuncSetAttribute(cfconv_kernel,
                         cudaFuncAttributeMaxDynamicSharedMemorySize, SMEM_BYTES);

    int n4 = out_size / 4;
    zero_kernel<<<(n4 + 255) / 256, 256>>>((float4*)out, n4);

    cfconv_kernel<<<304, THREADS, SMEM_BYTES>>>(nw, rbf, W1, b1, W2, b2, src, dst, out, E);
}